// round 1
// baseline (speedup 1.0000x reference)
#include <cuda_runtime.h>
#include <math.h>

#define BATCH 4
#define NSEQ 2048
#define DIM 1024
#define HEADS 16
#define DH 64
#define INNER 1024
#define NQKV 3072
#define ROWS (BATCH*NSEQ)

// Scratch (allocation is forbidden; __device__ globals are the sanctioned path)
__device__ float g_xn[(size_t)ROWS * DIM];     //  33.5 MB
__device__ float g_qkv[(size_t)ROWS * NQKV];   // 100.7 MB
__device__ float g_o[(size_t)ROWS * INNER];    //  33.5 MB

// ---------------------------------------------------------------------------
// LayerNorm: one block per row of 1024
// ---------------------------------------------------------------------------
__global__ __launch_bounds__(256) void ln_kernel(
    const float* __restrict__ x, const float* __restrict__ gg,
    const float* __restrict__ bb, float* __restrict__ out)
{
    int row = blockIdx.x;
    int tid = threadIdx.x;
    const float4* xr = (const float4*)(x + (size_t)row * DIM);
    float4 v = xr[tid];
    float s  = v.x + v.y + v.z + v.w;
    float s2 = fmaf(v.x, v.x, fmaf(v.y, v.y, fmaf(v.z, v.z, v.w * v.w)));
    #pragma unroll
    for (int o = 16; o; o >>= 1) {
        s  += __shfl_xor_sync(0xffffffffu, s, o);
        s2 += __shfl_xor_sync(0xffffffffu, s2, o);
    }
    __shared__ float rs[8], rs2[8];
    __shared__ float mu_s, rstd_s;
    int w = tid >> 5;
    if ((tid & 31) == 0) { rs[w] = s; rs2[w] = s2; }
    __syncthreads();
    if (tid == 0) {
        float a = 0.f, a2 = 0.f;
        #pragma unroll
        for (int i = 0; i < 8; i++) { a += rs[i]; a2 += rs2[i]; }
        float mu = a * (1.f / DIM);
        float var = a2 * (1.f / DIM) - mu * mu;
        mu_s = mu;
        rstd_s = rsqrtf(var + 1e-5f);
    }
    __syncthreads();
    float mu = mu_s, r = rstd_s;
    float4 g4 = ((const float4*)gg)[tid];
    float4 b4 = ((const float4*)bb)[tid];
    float4 o4;
    o4.x = (v.x - mu) * r * g4.x + b4.x;
    o4.y = (v.y - mu) * r * g4.y + b4.y;
    o4.z = (v.z - mu) * r * g4.z + b4.z;
    o4.w = (v.w - mu) * r * g4.w + b4.w;
    ((float4*)(out + (size_t)row * DIM))[tid] = o4;
}

// ---------------------------------------------------------------------------
// SGEMM: C[M,N] = A[M,K] @ B[K,N] (+ bias). All dims multiples of tile sizes.
// 128x128 block tile, BK=16, 8x8 per thread, 256 threads.
// ---------------------------------------------------------------------------
__global__ __launch_bounds__(256) void sgemm_kernel(
    const float* __restrict__ A, const float* __restrict__ B,
    const float* __restrict__ bias, float* __restrict__ C,
    int M, int N, int K, int has_bias)
{
    __shared__ float As[16][128];
    __shared__ float Bs[16][132];
    int tid = threadIdx.x;
    int tx = tid & 15, ty = tid >> 4;
    int rowbase = blockIdx.y * 128;
    int colbase = blockIdx.x * 128;
    int rm0 = ty * 8, cn0 = tx * 8;

    float acc[8][8];
    #pragma unroll
    for (int i = 0; i < 8; i++)
        #pragma unroll
        for (int j = 0; j < 8; j++) acc[i][j] = 0.f;

    for (int k0 = 0; k0 < K; k0 += 16) {
        #pragma unroll
        for (int t = 0; t < 2; t++) {
            int idx = tid * 2 + t;
            int ar = idx >> 2, ac4 = idx & 3;
            float4 v = *(const float4*)(A + (size_t)(rowbase + ar) * K + k0 + ac4 * 4);
            As[ac4 * 4 + 0][ar] = v.x;
            As[ac4 * 4 + 1][ar] = v.y;
            As[ac4 * 4 + 2][ar] = v.z;
            As[ac4 * 4 + 3][ar] = v.w;
        }
        #pragma unroll
        for (int t = 0; t < 2; t++) {
            int idx = tid * 2 + t;
            int br = idx >> 5, bc4 = idx & 31;
            float4 v = *(const float4*)(B + (size_t)(k0 + br) * N + colbase + bc4 * 4);
            *(float4*)&Bs[br][bc4 * 4] = v;
        }
        __syncthreads();
        #pragma unroll 8
        for (int k = 0; k < 16; k++) {
            float a[8], b[8];
            *(float4*)&a[0] = *(const float4*)&As[k][rm0];
            *(float4*)&a[4] = *(const float4*)&As[k][rm0 + 4];
            *(float4*)&b[0] = *(const float4*)&Bs[k][cn0];
            *(float4*)&b[4] = *(const float4*)&Bs[k][cn0 + 4];
            #pragma unroll
            for (int i = 0; i < 8; i++)
                #pragma unroll
                for (int j = 0; j < 8; j++)
                    acc[i][j] = fmaf(a[i], b[j], acc[i][j]);
        }
        __syncthreads();
    }

    float4 bi0 = make_float4(0.f, 0.f, 0.f, 0.f), bi1 = bi0;
    if (has_bias) {
        bi0 = *(const float4*)(bias + colbase + cn0);
        bi1 = *(const float4*)(bias + colbase + cn0 + 4);
    }
    #pragma unroll
    for (int i = 0; i < 8; i++) {
        size_t roff = (size_t)(rowbase + rm0 + i) * N + colbase + cn0;
        float4 v0, v1;
        v0.x = acc[i][0] + bi0.x; v0.y = acc[i][1] + bi0.y;
        v0.z = acc[i][2] + bi0.z; v0.w = acc[i][3] + bi0.w;
        v1.x = acc[i][4] + bi1.x; v1.y = acc[i][5] + bi1.y;
        v1.z = acc[i][6] + bi1.z; v1.w = acc[i][7] + bi1.w;
        *(float4*)(C + roff) = v0;
        *(float4*)(C + roff + 4) = v1;
    }
}

// ---------------------------------------------------------------------------
// RoPE in place on q,k. One thread owns the (d, d+32) pair -> no races.
// Faithful to the reference: cos index j uses inv_freq[j>>1] (interleaved
// tables) combined with half-rotation.
// ---------------------------------------------------------------------------
__global__ __launch_bounds__(256) void rope_kernel(float* __restrict__ qkv)
{
    int idx = blockIdx.x * blockDim.x + threadIdx.x;   // ROWS*1024 total
    int row = idx >> 10;
    int c2  = idx & 1023;
    int part = c2 >> 9;        // 0 = q, 1 = k
    int wi = c2 & 511;
    int h = wi >> 5;
    int dlo = wi & 31;
    int pos = row & (NSEQ - 1);
    size_t base = (size_t)row * NQKV + part * INNER + h * DH;
    float v0 = qkv[base + dlo];
    float v1 = qkv[base + dlo + 32];
    float i0f = (float)(dlo >> 1);
    float i1f = (float)((dlo + 32) >> 1);
    float f0 = powf(10000.f, -i0f * (1.f / 32.f));
    float f1 = powf(10000.f, -i1f * (1.f / 32.f));
    float a0 = (float)pos * f0;
    float a1 = (float)pos * f1;
    float c0, s0, c1, s1;
    sincosf(a0, &s0, &c0);
    sincosf(a1, &s1, &c1);
    qkv[base + dlo]      = v0 * c0 - v1 * s0;
    qkv[base + dlo + 32] = v1 * c1 + v0 * s1;
}

// ---------------------------------------------------------------------------
// Flash attention, fp32. Block = (64 q rows) x (head) x (batch). 256 threads.
// Q/K stored transposed in smem so the S-GEMM inner loop is pure LDS.128,
// conflict-free given the (tx,ty) warp layout.
// ---------------------------------------------------------------------------
#define SPITCH 68

__global__ __launch_bounds__(256) void attn_kernel(
    const float* __restrict__ qkv, float* __restrict__ o)
{
    extern __shared__ float sm[];
    float* QsT = sm;                   // [64][68]  QsT[d*68 + r]
    float* KsT = sm + 64 * SPITCH;     // [64][68]  KsT[d*68 + j]
    float* Vs  = sm + 2 * 64 * SPITCH; // [64][68]  Vs[j*68 + c]
    float* Ss  = sm + 3 * 64 * SPITCH; // [64][68]  Ss[i*68 + j]
    float* mrow = sm + 4 * 64 * SPITCH;
    float* lrow = mrow + 64;
    float* scl  = lrow + 64;

    int qt = blockIdx.x, h = blockIdx.y, b = blockIdx.z;
    int tid = threadIdx.x;
    int tx = tid & 15, ty = tid >> 4;
    int i0 = ty * 4, j0 = tx * 4;

    size_t qbase = ((size_t)(b * NSEQ + qt * 64)) * NQKV + h * DH;
    for (int i = tid; i < 4096; i += 256) {
        int r = i >> 6, d = i & 63;
        QsT[d * SPITCH + r] = qkv[qbase + (size_t)r * NQKV + d];
    }
    if (tid < 64) { mrow[tid] = -1e30f; lrow[tid] = 0.f; }

    float accO[4][4];
    #pragma unroll
    for (int i = 0; i < 4; i++)
        #pragma unroll
        for (int j = 0; j < 4; j++) accO[i][j] = 0.f;

    for (int kt = 0; kt < 32; kt++) {
        __syncthreads();   // previous PV done before K/V overwrite
        size_t kbase = ((size_t)(b * NSEQ + kt * 64)) * NQKV + INNER + h * DH;
        for (int i = tid; i < 4096; i += 256) {
            int r = i >> 6, d = i & 63;
            KsT[d * SPITCH + r] = qkv[kbase + (size_t)r * NQKV + d];
            Vs[r * SPITCH + d]  = qkv[kbase + INNER + (size_t)r * NQKV + d];
        }
        __syncthreads();

        // S = scale * Q K^T, 4x4 per thread
        float acc[4][4];
        #pragma unroll
        for (int i = 0; i < 4; i++)
            #pragma unroll
            for (int j = 0; j < 4; j++) acc[i][j] = 0.f;
        #pragma unroll 8
        for (int d = 0; d < 64; d++) {
            float4 q4 = *(const float4*)&QsT[d * SPITCH + i0];
            float4 k4 = *(const float4*)&KsT[d * SPITCH + j0];
            float qa[4] = {q4.x, q4.y, q4.z, q4.w};
            float ka[4] = {k4.x, k4.y, k4.z, k4.w};
            #pragma unroll
            for (int ii = 0; ii < 4; ii++)
                #pragma unroll
                for (int jj = 0; jj < 4; jj++)
                    acc[ii][jj] = fmaf(qa[ii], ka[jj], acc[ii][jj]);
        }
        const float scale = 0.125f;   // 1/sqrt(64)
        #pragma unroll
        for (int ii = 0; ii < 4; ii++) {
            float4 v;
            v.x = acc[ii][0] * scale; v.y = acc[ii][1] * scale;
            v.z = acc[ii][2] * scale; v.w = acc[ii][3] * scale;
            *(float4*)&Ss[(i0 + ii) * SPITCH + j0] = v;
        }
        __syncthreads();

        // Online softmax: 4 lanes per row
        {
            int r = tid >> 2, qq = tid & 3;
            float* srow = &Ss[r * SPITCH + qq * 16];
            float mx = -1e30f;
            #pragma unroll
            for (int j = 0; j < 16; j++) mx = fmaxf(mx, srow[j]);
            mx = fmaxf(mx, __shfl_xor_sync(0xffffffffu, mx, 1));
            mx = fmaxf(mx, __shfl_xor_sync(0xffffffffu, mx, 2));
            float mold = mrow[r];
            float newm = fmaxf(mold, mx);
            float sum = 0.f;
            #pragma unroll
            for (int j = 0; j < 16; j++) {
                float p = expf(srow[j] - newm);
                srow[j] = p;
                sum += p;
            }
            sum += __shfl_xor_sync(0xffffffffu, sum, 1);
            sum += __shfl_xor_sync(0xffffffffu, sum, 2);
            if (qq == 0) {
                float sc = expf(mold - newm);
                scl[r] = sc;
                lrow[r] = lrow[r] * sc + sum;
                mrow[r] = newm;
            }
        }
        __syncthreads();

        // Rescale accumulators, then O += P V
        #pragma unroll
        for (int ii = 0; ii < 4; ii++) {
            float sc = scl[i0 + ii];
            #pragma unroll
            for (int jj = 0; jj < 4; jj++) accO[ii][jj] *= sc;
        }
        #pragma unroll 4
        for (int jb = 0; jb < 16; jb++) {
            float pa[4][4], va[4][4];
            #pragma unroll
            for (int ii = 0; ii < 4; ii++) {
                float4 p4 = *(const float4*)&Ss[(i0 + ii) * SPITCH + jb * 4];
                pa[ii][0] = p4.x; pa[ii][1] = p4.y; pa[ii][2] = p4.z; pa[ii][3] = p4.w;
            }
            #pragma unroll
            for (int r = 0; r < 4; r++) {
                float4 v4 = *(const float4*)&Vs[(jb * 4 + r) * SPITCH + j0];
                va[r][0] = v4.x; va[r][1] = v4.y; va[r][2] = v4.z; va[r][3] = v4.w;
            }
            #pragma unroll
            for (int ii = 0; ii < 4; ii++)
                #pragma unroll
                for (int r = 0; r < 4; r++)
                    #pragma unroll
                    for (int jj = 0; jj < 4; jj++)
                        accO[ii][jj] = fmaf(pa[ii][r], va[r][jj], accO[ii][jj]);
        }
    }

    size_t obase = ((size_t)(b * NSEQ + qt * 64)) * INNER + h * DH;
    #pragma unroll
    for (int ii = 0; ii < 4; ii++) {
        float inv = 1.f / lrow[i0 + ii];
        float4 vo;
        vo.x = accO[ii][0] * inv; vo.y = accO[ii][1] * inv;
        vo.z = accO[ii][2] * inv; vo.w = accO[ii][3] * inv;
        *(float4*)(o + obase + (size_t)(i0 + ii) * INNER + j0) = vo;
    }
}

// ---------------------------------------------------------------------------
extern "C" void kernel_launch(void* const* d_in, const int* in_sizes, int n_in,
                              void* d_out, int out_size)
{
    const float* x     = (const float*)d_in[0];
    const float* ln_g  = (const float*)d_in[1];
    const float* ln_b  = (const float*)d_in[2];
    const float* w_qkv = (const float*)d_in[3];
    const float* w_out = (const float*)d_in[4];
    const float* b_out = (const float*)d_in[5];
    float* out = (float*)d_out;

    float *xn, *qkv, *o;
    cudaGetSymbolAddress((void**)&xn,  g_xn);
    cudaGetSymbolAddress((void**)&qkv, g_qkv);
    cudaGetSymbolAddress((void**)&o,   g_o);

    ln_kernel<<<ROWS, 256>>>(x, ln_g, ln_b, xn);

    dim3 g1(NQKV / 128, ROWS / 128);
    sgemm_kernel<<<g1, 256>>>(xn, w_qkv, nullptr, qkv, ROWS, NQKV, DIM, 0);

    rope_kernel<<<(ROWS * 1024) / 256, 256>>>(qkv);

    int smem = (4 * 64 * SPITCH + 3 * 64) * (int)sizeof(float);
    cudaFuncSetAttribute(attn_kernel, cudaFuncAttributeMaxDynamicSharedMemorySize, smem);
    attn_kernel<<<dim3(NSEQ / 64, HEADS, BATCH), 256, smem>>>(qkv, o);

    dim3 g2(DIM / 128, ROWS / 128);
    sgemm_kernel<<<g2, 256>>>(o, w_out, b_out, out, ROWS, DIM, INNER, 1);
}

// round 3
// speedup vs baseline: 1.6677x; 1.6677x over previous
#include <cuda_runtime.h>
#include <cuda_fp16.h>
#include <math.h>
#include <stdint.h>

#define BATCH 4
#define NSEQ 2048
#define DIM 1024
#define HEADS 16
#define DH 64
#define INNER 1024
#define NQKV 3072
#define ROWS (BATCH*NSEQ)

// Scratch (__device__ globals are the sanctioned path)
__device__ __half g_xn_h[(size_t)ROWS * DIM];        // 16.8 MB
__device__ float  g_qkv[(size_t)ROWS * NQKV];        // 100.7 MB
__device__ __half g_o_h[(size_t)ROWS * INNER];       // 16.8 MB
__device__ __half g_wqkvT_h[(size_t)NQKV * DIM];     // 6.3 MB  (W_qkv^T [N][K])
__device__ __half g_woutT_h[(size_t)DIM * INNER];    // 2.1 MB  (W_out^T [N][K])

__device__ __forceinline__ uint32_t smem_u32(const void* p) {
    uint32_t a;
    asm("{ .reg .u64 t; cvta.to.shared.u64 t, %1; cvt.u32.u64 %0, t; }"
        : "=r"(a) : "l"(p));
    return a;
}
__device__ __forceinline__ void cp_async16(uint32_t dst, const void* src) {
    asm volatile("cp.async.cg.shared.global [%0], [%1], 16;"
                 :: "r"(dst), "l"(src) : "memory");
}
__device__ __forceinline__ void ldsm4(uint32_t* r, uint32_t addr) {
    asm volatile("ldmatrix.sync.aligned.m8n8.x4.shared.b16 {%0,%1,%2,%3}, [%4];"
                 : "=r"(r[0]), "=r"(r[1]), "=r"(r[2]), "=r"(r[3]) : "r"(addr));
}
__device__ __forceinline__ void mma16816(float* c, const uint32_t* a, uint32_t b0, uint32_t b1) {
    asm volatile(
        "mma.sync.aligned.m16n8k16.row.col.f32.f16.f16.f32 "
        "{%0,%1,%2,%3}, {%4,%5,%6,%7}, {%8,%9}, {%0,%1,%2,%3};"
        : "+f"(c[0]), "+f"(c[1]), "+f"(c[2]), "+f"(c[3])
        : "r"(a[0]), "r"(a[1]), "r"(a[2]), "r"(a[3]), "r"(b0), "r"(b1));
}

// ---------------------------------------------------------------------------
// LayerNorm -> half output
// ---------------------------------------------------------------------------
__global__ __launch_bounds__(256) void ln_kernel(
    const float* __restrict__ x, const float* __restrict__ gg,
    const float* __restrict__ bb, __half* __restrict__ out)
{
    int row = blockIdx.x;
    int tid = threadIdx.x;
    const float4* xr = (const float4*)(x + (size_t)row * DIM);
    float4 v = xr[tid];
    float s  = v.x + v.y + v.z + v.w;
    float s2 = fmaf(v.x, v.x, fmaf(v.y, v.y, fmaf(v.z, v.z, v.w * v.w)));
    #pragma unroll
    for (int o = 16; o; o >>= 1) {
        s  += __shfl_xor_sync(0xffffffffu, s, o);
        s2 += __shfl_xor_sync(0xffffffffu, s2, o);
    }
    __shared__ float rs[8], rs2[8];
    __shared__ float mu_s, rstd_s;
    int w = tid >> 5;
    if ((tid & 31) == 0) { rs[w] = s; rs2[w] = s2; }
    __syncthreads();
    if (tid == 0) {
        float a = 0.f, a2 = 0.f;
        #pragma unroll
        for (int i = 0; i < 8; i++) { a += rs[i]; a2 += rs2[i]; }
        float mu = a * (1.f / DIM);
        float var = a2 * (1.f / DIM) - mu * mu;
        mu_s = mu;
        rstd_s = rsqrtf(var + 1e-5f);
    }
    __syncthreads();
    float mu = mu_s, r = rstd_s;
    float4 g4 = ((const float4*)gg)[tid];
    float4 b4 = ((const float4*)bb)[tid];
    float o0 = (v.x - mu) * r * g4.x + b4.x;
    float o1 = (v.y - mu) * r * g4.y + b4.y;
    float o2 = (v.z - mu) * r * g4.z + b4.z;
    float o3 = (v.w - mu) * r * g4.w + b4.w;
    __half2* orow = (__half2*)(out + (size_t)row * DIM);
    orow[tid * 2]     = __floats2half2_rn(o0, o1);
    orow[tid * 2 + 1] = __floats2half2_rn(o2, o3);
}

// ---------------------------------------------------------------------------
// Weight transpose + fp32->fp16: src[K][N] -> dst[N][K]
// ---------------------------------------------------------------------------
__global__ __launch_bounds__(256) void transpose_cvt_kernel(
    const float* __restrict__ src, __half* __restrict__ dst, int K, int N)
{
    __shared__ float t[32][33];
    int n0 = blockIdx.x * 32, k0 = blockIdx.y * 32;
    int tx = threadIdx.x & 31, ty = threadIdx.x >> 5;
    #pragma unroll
    for (int i = 0; i < 4; i++)
        t[ty + 8 * i][tx] = src[(size_t)(k0 + ty + 8 * i) * N + n0 + tx];
    __syncthreads();
    #pragma unroll
    for (int i = 0; i < 4; i++)
        dst[(size_t)(n0 + ty + 8 * i) * K + k0 + tx] = __float2half(t[tx][ty + 8 * i]);
}

// ---------------------------------------------------------------------------
// HGEMM: C[M,N](fp32) = A[M,K](h) @ BT[N,K](h)^T (+bias)
// 128x128x32 tile, 8 warps (64x32 each), cp.async double buffer, ldmatrix.
// ---------------------------------------------------------------------------
__global__ __launch_bounds__(256) void hgemm(
    const __half* __restrict__ A, const __half* __restrict__ BT,
    const float* __restrict__ bias, float* __restrict__ C,
    int M, int N, int K, int has_bias)
{
    __shared__ __align__(128) char sm[32768];  // A:2x8KB, B:2x8KB
    uint32_t sbase = smem_u32(sm);
    int tid = threadIdx.x, lane = tid & 31, wid = tid >> 5;
    int wm = (wid >> 2) * 64, wn = (wid & 3) * 32;
    int row0 = blockIdx.y * 128, col0 = blockIdx.x * 128;

    const __half* Ag = A  + (size_t)row0 * K;
    const __half* Bg = BT + (size_t)col0 * K;

    float acc[4][4][4];
    #pragma unroll
    for (int i = 0; i < 4; i++)
        #pragma unroll
        for (int j = 0; j < 4; j++)
            #pragma unroll
            for (int q = 0; q < 4; q++) acc[i][j][q] = 0.f;

    // swizzled smem chunk address: row r (0..127, 64B row), chunk c (0..3, 16B)
    #define SWA(base, r, c) ((base) + (uint32_t)((r) * 64 + (((c) ^ (((r) >> 1) & 3)) * 16)))

    // stage load: 512 A-chunks + 512 B-chunks, 256 threads -> 2+2 each
    #define LOAD_STAGE(stage, k0)                                              \
    {                                                                          \
        uint32_t abase = sbase + (stage) * 8192;                               \
        uint32_t bbase = sbase + 16384 + (stage) * 8192;                       \
        _Pragma("unroll")                                                      \
        for (int t = 0; t < 2; t++) {                                          \
            int idx = tid + t * 256;                                           \
            int r = idx >> 2, c = idx & 3;                                     \
            cp_async16(SWA(abase, r, c), Ag + (size_t)r * K + (k0) + c * 8);   \
            cp_async16(SWA(bbase, r, c), Bg + (size_t)r * K + (k0) + c * 8);   \
        }                                                                      \
        asm volatile("cp.async.commit_group;" ::: "memory");                   \
    }

    LOAD_STAGE(0, 0);
    const int NK = K >> 5;
    for (int kt = 0; kt < NK; kt++) {
        int cur = kt & 1;
        if (kt + 1 < NK) {
            LOAD_STAGE(1 - cur, (kt + 1) << 5);
            asm volatile("cp.async.wait_group 1;" ::: "memory");
        } else {
            asm volatile("cp.async.wait_group 0;" ::: "memory");
        }
        __syncthreads();

        uint32_t abase = sbase + cur * 8192;
        uint32_t bbase = sbase + 16384 + cur * 8192;
        #pragma unroll
        for (int ks = 0; ks < 2; ks++) {
            uint32_t a[4][4], b[2][4];
            #pragma unroll
            for (int mf = 0; mf < 4; mf++) {
                int rr = wm + mf * 16 + ((lane >> 3) & 1) * 8 + (lane & 7);
                int cc = ks * 2 + (lane >> 4);
                ldsm4(a[mf], SWA(abase, rr, cc));
            }
            #pragma unroll
            for (int n2 = 0; n2 < 2; n2++) {
                int rr = wn + n2 * 16 + ((lane >> 4) & 1) * 8 + (lane & 7);
                int cc = ks * 2 + ((lane >> 3) & 1);
                ldsm4(b[n2], SWA(bbase, rr, cc));
            }
            #pragma unroll
            for (int mf = 0; mf < 4; mf++)
                #pragma unroll
                for (int nf = 0; nf < 4; nf++)
                    mma16816(acc[mf][nf], a[mf],
                             b[nf >> 1][(nf & 1) * 2], b[nf >> 1][(nf & 1) * 2 + 1]);
        }
        __syncthreads();
    }

    // Epilogue: c0,c1 -> (row, col..col+1), c2,c3 -> (row+8, ...)
    #pragma unroll
    for (int mf = 0; mf < 4; mf++) {
        int grow = row0 + wm + mf * 16 + (lane >> 2);
        #pragma unroll
        for (int nf = 0; nf < 4; nf++) {
            int gcol = col0 + wn + nf * 8 + (lane & 3) * 2;
            float bx = 0.f, by = 0.f;
            if (has_bias) {
                float2 bb = *(const float2*)(bias + gcol);
                bx = bb.x; by = bb.y;
            }
            float2 v0 = make_float2(acc[mf][nf][0] + bx, acc[mf][nf][1] + by);
            float2 v1 = make_float2(acc[mf][nf][2] + bx, acc[mf][nf][3] + by);
            *(float2*)(C + (size_t)grow * N + gcol) = v0;
            *(float2*)(C + (size_t)(grow + 8) * N + gcol) = v1;
        }
    }
}

// ---------------------------------------------------------------------------
// RoPE in place on q,k (fp32 qkv)
// ---------------------------------------------------------------------------
__global__ __launch_bounds__(256) void rope_kernel(float* __restrict__ qkv)
{
    int idx = blockIdx.x * blockDim.x + threadIdx.x;
    int row = idx >> 10;
    int c2  = idx & 1023;
    int part = c2 >> 9;
    int wi = c2 & 511;
    int h = wi >> 5;
    int dlo = wi & 31;
    int pos = row & (NSEQ - 1);
    size_t base = (size_t)row * NQKV + part * INNER + h * DH;
    float v0 = qkv[base + dlo];
    float v1 = qkv[base + dlo + 32];
    float i0f = (float)(dlo >> 1);
    float i1f = (float)((dlo + 32) >> 1);
    float f0 = powf(10000.f, -i0f * (1.f / 32.f));
    float f1 = powf(10000.f, -i1f * (1.f / 32.f));
    float a0 = (float)pos * f0;
    float a1 = (float)pos * f1;
    float c0, s0, c1, s1;
    sincosf(a0, &s0, &c0);
    sincosf(a1, &s1, &c1);
    qkv[base + dlo]      = v0 * c0 - v1 * s0;
    qkv[base + dlo + 32] = v1 * c1 + v0 * s1;
}

// ---------------------------------------------------------------------------
// Flash attention fp32 SIMT; output converted to half for the out-proj GEMM
// ---------------------------------------------------------------------------
#define SPITCH 68

__global__ __launch_bounds__(256) void attn_kernel(
    const float* __restrict__ qkv, __half* __restrict__ o)
{
    extern __shared__ float smf[];
    float* QsT = smf;
    float* KsT = smf + 64 * SPITCH;
    float* Vs  = smf + 2 * 64 * SPITCH;
    float* Ss  = smf + 3 * 64 * SPITCH;
    float* mrow = smf + 4 * 64 * SPITCH;
    float* lrow = mrow + 64;
    float* scl  = lrow + 64;

    int qt = blockIdx.x, h = blockIdx.y, b = blockIdx.z;
    int tid = threadIdx.x;
    int tx = tid & 15, ty = tid >> 4;
    int i0 = ty * 4, j0 = tx * 4;

    size_t qbase = ((size_t)(b * NSEQ + qt * 64)) * NQKV + h * DH;
    for (int i = tid; i < 4096; i += 256) {
        int r = i >> 6, d = i & 63;
        QsT[d * SPITCH + r] = qkv[qbase + (size_t)r * NQKV + d];
    }
    if (tid < 64) { mrow[tid] = -1e30f; lrow[tid] = 0.f; }

    float accO[4][4];
    #pragma unroll
    for (int i = 0; i < 4; i++)
        #pragma unroll
        for (int j = 0; j < 4; j++) accO[i][j] = 0.f;

    for (int kt = 0; kt < 32; kt++) {
        __syncthreads();
        size_t kbase = ((size_t)(b * NSEQ + kt * 64)) * NQKV + INNER + h * DH;
        for (int i = tid; i < 4096; i += 256) {
            int r = i >> 6, d = i & 63;
            KsT[d * SPITCH + r] = qkv[kbase + (size_t)r * NQKV + d];
            Vs[r * SPITCH + d]  = qkv[kbase + INNER + (size_t)r * NQKV + d];
        }
        __syncthreads();

        float acc[4][4];
        #pragma unroll
        for (int i = 0; i < 4; i++)
            #pragma unroll
            for (int j = 0; j < 4; j++) acc[i][j] = 0.f;
        #pragma unroll 8
        for (int d = 0; d < 64; d++) {
            float4 q4 = *(const float4*)&QsT[d * SPITCH + i0];
            float4 k4 = *(const float4*)&KsT[d * SPITCH + j0];
            float qa[4] = {q4.x, q4.y, q4.z, q4.w};
            float ka[4] = {k4.x, k4.y, k4.z, k4.w};
            #pragma unroll
            for (int ii = 0; ii < 4; ii++)
                #pragma unroll
                for (int jj = 0; jj < 4; jj++)
                    acc[ii][jj] = fmaf(qa[ii], ka[jj], acc[ii][jj]);
        }
        const float scale = 0.125f;
        #pragma unroll
        for (int ii = 0; ii < 4; ii++) {
            float4 v;
            v.x = acc[ii][0] * scale; v.y = acc[ii][1] * scale;
            v.z = acc[ii][2] * scale; v.w = acc[ii][3] * scale;
            *(float4*)&Ss[(i0 + ii) * SPITCH + j0] = v;
        }
        __syncthreads();

        {
            int r = tid >> 2, qq = tid & 3;
            float* srow = &Ss[r * SPITCH + qq * 16];
            float mx = -1e30f;
            #pragma unroll
            for (int j = 0; j < 16; j++) mx = fmaxf(mx, srow[j]);
            mx = fmaxf(mx, __shfl_xor_sync(0xffffffffu, mx, 1));
            mx = fmaxf(mx, __shfl_xor_sync(0xffffffffu, mx, 2));
            float mold = mrow[r];
            float newm = fmaxf(mold, mx);
            float sum = 0.f;
            #pragma unroll
            for (int j = 0; j < 16; j++) {
                float p = expf(srow[j] - newm);
                srow[j] = p;
                sum += p;
            }
            sum += __shfl_xor_sync(0xffffffffu, sum, 1);
            sum += __shfl_xor_sync(0xffffffffu, sum, 2);
            if (qq == 0) {
                float sc = expf(mold - newm);
                scl[r] = sc;
                lrow[r] = lrow[r] * sc + sum;
                mrow[r] = newm;
            }
        }
        __syncthreads();

        #pragma unroll
        for (int ii = 0; ii < 4; ii++) {
            float sc = scl[i0 + ii];
            #pragma unroll
            for (int jj = 0; jj < 4; jj++) accO[ii][jj] *= sc;
        }
        #pragma unroll 4
        for (int jb = 0; jb < 16; jb++) {
            float pa[4][4], va[4][4];
            #pragma unroll
            for (int ii = 0; ii < 4; ii++) {
                float4 p4 = *(const float4*)&Ss[(i0 + ii) * SPITCH + jb * 4];
                pa[ii][0] = p4.x; pa[ii][1] = p4.y; pa[ii][2] = p4.z; pa[ii][3] = p4.w;
            }
            #pragma unroll
            for (int r = 0; r < 4; r++) {
                float4 v4 = *(const float4*)&Vs[(jb * 4 + r) * SPITCH + j0];
                va[r][0] = v4.x; va[r][1] = v4.y; va[r][2] = v4.z; va[r][3] = v4.w;
            }
            #pragma unroll
            for (int ii = 0; ii < 4; ii++)
                #pragma unroll
                for (int r = 0; r < 4; r++)
                    #pragma unroll
                    for (int jj = 0; jj < 4; jj++)
                        accO[ii][jj] = fmaf(pa[ii][r], va[r][jj], accO[ii][jj]);
        }
    }

    size_t obase = ((size_t)(b * NSEQ + qt * 64)) * INNER + h * DH;
    #pragma unroll
    for (int ii = 0; ii < 4; ii++) {
        float inv = 1.f / lrow[i0 + ii];
        __half2* orow = (__half2*)(o + obase + (size_t)(i0 + ii) * INNER + j0);
        orow[0] = __floats2half2_rn(accO[ii][0] * inv, accO[ii][1] * inv);
        orow[1] = __floats2half2_rn(accO[ii][2] * inv, accO[ii][3] * inv);
    }
}

// ---------------------------------------------------------------------------
extern "C" void kernel_launch(void* const* d_in, const int* in_sizes, int n_in,
                              void* d_out, int out_size)
{
    const float* x     = (const float*)d_in[0];
    const float* ln_g  = (const float*)d_in[1];
    const float* ln_b  = (const float*)d_in[2];
    const float* w_qkv = (const float*)d_in[3];
    const float* w_out = (const float*)d_in[4];
    const float* b_out = (const float*)d_in[5];
    float* out = (float*)d_out;

    __half *xn_h, *o_h, *wqkvT_h, *woutT_h;
    float *qkv;
    cudaGetSymbolAddress((void**)&xn_h,    g_xn_h);
    cudaGetSymbolAddress((void**)&qkv,     g_qkv);
    cudaGetSymbolAddress((void**)&o_h,     g_o_h);
    cudaGetSymbolAddress((void**)&wqkvT_h, g_wqkvT_h);
    cudaGetSymbolAddress((void**)&woutT_h, g_woutT_h);

    static int smem_set = 0;
    int asmem = (4 * 64 * SPITCH + 3 * 64) * (int)sizeof(float);
    if (!smem_set) {
        cudaFuncSetAttribute(attn_kernel, cudaFuncAttributeMaxDynamicSharedMemorySize, asmem);
        smem_set = 1;
    }

    ln_kernel<<<ROWS, 256>>>(x, ln_g, ln_b, xn_h);
    transpose_cvt_kernel<<<dim3(NQKV / 32, DIM / 32), 256>>>(w_qkv, wqkvT_h, DIM, NQKV);
    transpose_cvt_kernel<<<dim3(DIM / 32, INNER / 32), 256>>>(w_out, woutT_h, INNER, DIM);

    hgemm<<<dim3(NQKV / 128, ROWS / 128), 256>>>(
        xn_h, wqkvT_h, nullptr, qkv, ROWS, NQKV, DIM, 0);

    rope_kernel<<<(ROWS * 1024) / 256, 256>>>(qkv);

    attn_kernel<<<dim3(NSEQ / 64, HEADS, BATCH), 256, asmem>>>(qkv, o_h);

    hgemm<<<dim3(DIM / 128, ROWS / 128), 256>>>(
        o_h, woutT_h, b_out, out, ROWS, DIM, INNER, 1);
}

// round 4
// speedup vs baseline: 3.6797x; 2.2065x over previous
#include <cuda_runtime.h>
#include <cuda_fp16.h>
#include <math.h>
#include <stdint.h>

#define BATCH 4
#define NSEQ 2048
#define DIM 1024
#define HEADS 16
#define DH 64
#define INNER 1024
#define NQKV 3072
#define ROWS (BATCH*NSEQ)

// Scratch (__device__ globals are the sanctioned path)
__device__ __half g_xn_h[(size_t)ROWS * DIM];
__device__ float  g_qkv[(size_t)ROWS * NQKV];
__device__ __half g_o_h[(size_t)ROWS * INNER];
__device__ __half g_wqkvT_h[(size_t)NQKV * DIM];
__device__ __half g_woutT_h[(size_t)DIM * INNER];
__device__ float  g_cosT[(size_t)NSEQ * DH];
__device__ float  g_sinT[(size_t)NSEQ * DH];

__device__ __forceinline__ uint32_t smem_u32(const void* p) {
    uint32_t a;
    asm("{ .reg .u64 t; cvta.to.shared.u64 t, %1; cvt.u32.u64 %0, t; }"
        : "=r"(a) : "l"(p));
    return a;
}
__device__ __forceinline__ void cp_async16(uint32_t dst, const void* src) {
    asm volatile("cp.async.cg.shared.global [%0], [%1], 16;"
                 :: "r"(dst), "l"(src) : "memory");
}
__device__ __forceinline__ void ldsm4(uint32_t* r, uint32_t addr) {
    asm volatile("ldmatrix.sync.aligned.m8n8.x4.shared.b16 {%0,%1,%2,%3}, [%4];"
                 : "=r"(r[0]), "=r"(r[1]), "=r"(r[2]), "=r"(r[3]) : "r"(addr));
}
__device__ __forceinline__ void ldsm4t(uint32_t* r, uint32_t addr) {
    asm volatile("ldmatrix.sync.aligned.m8n8.x4.trans.shared.b16 {%0,%1,%2,%3}, [%4];"
                 : "=r"(r[0]), "=r"(r[1]), "=r"(r[2]), "=r"(r[3]) : "r"(addr));
}
__device__ __forceinline__ void mma16816(float* c, const uint32_t* a, uint32_t b0, uint32_t b1) {
    asm volatile(
        "mma.sync.aligned.m16n8k16.row.col.f32.f16.f16.f32 "
        "{%0,%1,%2,%3}, {%4,%5,%6,%7}, {%8,%9}, {%0,%1,%2,%3};"
        : "+f"(c[0]), "+f"(c[1]), "+f"(c[2]), "+f"(c[3])
        : "r"(a[0]), "r"(a[1]), "r"(a[2]), "r"(a[3]), "r"(b0), "r"(b1));
}
// FFMA-only 2^x for x <= 0 (no MUFU) — keeps the tensor pipe the bottleneck
__device__ __forceinline__ float exp2p(float x) {
    x = fmaxf(x, -126.f);
    float t = x + 12582912.f;      // round-to-nearest-int trick
    float fi = t - 12582912.f;
    float f = x - fi;              // [-0.5, 0.5]
    float p = 1.3333558146e-3f;
    p = fmaf(p, f, 9.6181291076e-3f);
    p = fmaf(p, f, 5.5504108665e-2f);
    p = fmaf(p, f, 2.4022650696e-1f);
    p = fmaf(p, f, 6.9314718056e-1f);
    p = fmaf(p, f, 1.0f);
    int ei = (int)fi;
    return __int_as_float(__float_as_int(p) + (ei << 23));
}
__device__ __forceinline__ uint32_t pack_h2(__half a, __half b) {
    __half2 t = __halves2half2(a, b);
    return *reinterpret_cast<uint32_t*>(&t);
}
// fp32 -> (hi, lo) fp16 pair for compensated MMA
__device__ __forceinline__ void hilo2(float a, float b, uint32_t& hi, uint32_t& lo) {
    __half ha = __float2half_rn(a), hb = __float2half_rn(b);
    hi = pack_h2(ha, hb);
    lo = pack_h2(__float2half_rn(a - __half2float(ha)),
                 __float2half_rn(b - __half2float(hb)));
}
// load 8 fp32, scale, split hi/lo, store 16B each into smem
__device__ __forceinline__ void stage_hilo8(const float* src, float scale,
                                            char* dhi, char* dlo) {
    float4 v0 = *(const float4*)src, v1 = *(const float4*)(src + 4);
    float f[8] = {v0.x*scale, v0.y*scale, v0.z*scale, v0.w*scale,
                  v1.x*scale, v1.y*scale, v1.z*scale, v1.w*scale};
    uint32_t ph[4], pl[4];
    #pragma unroll
    for (int i = 0; i < 4; i++) hilo2(f[2*i], f[2*i+1], ph[i], pl[i]);
    *(uint4*)dhi = make_uint4(ph[0], ph[1], ph[2], ph[3]);
    *(uint4*)dlo = make_uint4(pl[0], pl[1], pl[2], pl[3]);
}
// 128B-row swizzle: row r, 16B granule g (0..7)
#define SWZ(r, g) ((uint32_t)((r) * 128 + (((g) ^ ((r) & 7)) * 16)))

// ---------------------------------------------------------------------------
// LayerNorm -> half
// ---------------------------------------------------------------------------
__global__ __launch_bounds__(256) void ln_kernel(
    const float* __restrict__ x, const float* __restrict__ gg,
    const float* __restrict__ bb, __half* __restrict__ out)
{
    int row = blockIdx.x;
    int tid = threadIdx.x;
    const float4* xr = (const float4*)(x + (size_t)row * DIM);
    float4 v = xr[tid];
    float s  = v.x + v.y + v.z + v.w;
    float s2 = fmaf(v.x, v.x, fmaf(v.y, v.y, fmaf(v.z, v.z, v.w * v.w)));
    #pragma unroll
    for (int o = 16; o; o >>= 1) {
        s  += __shfl_xor_sync(0xffffffffu, s, o);
        s2 += __shfl_xor_sync(0xffffffffu, s2, o);
    }
    __shared__ float rs[8], rs2[8];
    __shared__ float mu_s, rstd_s;
    int w = tid >> 5;
    if ((tid & 31) == 0) { rs[w] = s; rs2[w] = s2; }
    __syncthreads();
    if (tid == 0) {
        float a = 0.f, a2 = 0.f;
        #pragma unroll
        for (int i = 0; i < 8; i++) { a += rs[i]; a2 += rs2[i]; }
        float mu = a * (1.f / DIM);
        float var = a2 * (1.f / DIM) - mu * mu;
        mu_s = mu;
        rstd_s = rsqrtf(var + 1e-5f);
    }
    __syncthreads();
    float mu = mu_s, r = rstd_s;
    float4 g4 = ((const float4*)gg)[tid];
    float4 b4 = ((const float4*)bb)[tid];
    __half2* orow = (__half2*)(out + (size_t)row * DIM);
    orow[tid * 2]     = __floats2half2_rn((v.x - mu) * r * g4.x + b4.x,
                                          (v.y - mu) * r * g4.y + b4.y);
    orow[tid * 2 + 1] = __floats2half2_rn((v.z - mu) * r * g4.z + b4.z,
                                          (v.w - mu) * r * g4.w + b4.w);
}

__global__ __launch_bounds__(256) void transpose_cvt_kernel(
    const float* __restrict__ src, __half* __restrict__ dst, int K, int N)
{
    __shared__ float t[32][33];
    int n0 = blockIdx.x * 32, k0 = blockIdx.y * 32;
    int tx = threadIdx.x & 31, ty = threadIdx.x >> 5;
    #pragma unroll
    for (int i = 0; i < 4; i++)
        t[ty + 8 * i][tx] = src[(size_t)(k0 + ty + 8 * i) * N + n0 + tx];
    __syncthreads();
    #pragma unroll
    for (int i = 0; i < 4; i++)
        dst[(size_t)(n0 + ty + 8 * i) * K + k0 + tx] = __float2half(t[tx][ty + 8 * i]);
}

// ---------------------------------------------------------------------------
// HGEMM (unchanged from R3): C fp32 = A(h) @ BT(h)^T
// ---------------------------------------------------------------------------
__global__ __launch_bounds__(256) void hgemm(
    const __half* __restrict__ A, const __half* __restrict__ BT,
    const float* __restrict__ bias, float* __restrict__ C,
    int M, int N, int K, int has_bias)
{
    __shared__ __align__(128) char sm[32768];
    uint32_t sbase = smem_u32(sm);
    int tid = threadIdx.x, lane = tid & 31, wid = tid >> 5;
    int wm = (wid >> 2) * 64, wn = (wid & 3) * 32;
    int row0 = blockIdx.y * 128, col0 = blockIdx.x * 128;
    const __half* Ag = A  + (size_t)row0 * K;
    const __half* Bg = BT + (size_t)col0 * K;

    float acc[4][4][4];
    #pragma unroll
    for (int i = 0; i < 4; i++)
        #pragma unroll
        for (int j = 0; j < 4; j++)
            #pragma unroll
            for (int q = 0; q < 4; q++) acc[i][j][q] = 0.f;

    #define SWA(base, r, c) ((base) + (uint32_t)((r) * 64 + (((c) ^ (((r) >> 1) & 3)) * 16)))
    #define LOAD_STAGE(stage, k0)                                              \
    {                                                                          \
        uint32_t abase = sbase + (stage) * 8192;                               \
        uint32_t bbase = sbase + 16384 + (stage) * 8192;                       \
        _Pragma("unroll")                                                      \
        for (int t = 0; t < 2; t++) {                                          \
            int idx = tid + t * 256;                                           \
            int r = idx >> 2, c = idx & 3;                                     \
            cp_async16(SWA(abase, r, c), Ag + (size_t)r * K + (k0) + c * 8);   \
            cp_async16(SWA(bbase, r, c), Bg + (size_t)r * K + (k0) + c * 8);   \
        }                                                                      \
        asm volatile("cp.async.commit_group;" ::: "memory");                   \
    }

    LOAD_STAGE(0, 0);
    const int NK = K >> 5;
    for (int kt = 0; kt < NK; kt++) {
        int cur = kt & 1;
        if (kt + 1 < NK) {
            LOAD_STAGE(1 - cur, (kt + 1) << 5);
            asm volatile("cp.async.wait_group 1;" ::: "memory");
        } else {
            asm volatile("cp.async.wait_group 0;" ::: "memory");
        }
        __syncthreads();
        uint32_t abase = sbase + cur * 8192;
        uint32_t bbase = sbase + 16384 + cur * 8192;
        #pragma unroll
        for (int ks = 0; ks < 2; ks++) {
            uint32_t a[4][4], b[2][4];
            #pragma unroll
            for (int mf = 0; mf < 4; mf++) {
                int rr = wm + mf * 16 + ((lane >> 3) & 1) * 8 + (lane & 7);
                int cc = ks * 2 + (lane >> 4);
                ldsm4(a[mf], SWA(abase, rr, cc));
            }
            #pragma unroll
            for (int n2 = 0; n2 < 2; n2++) {
                int rr = wn + n2 * 16 + ((lane >> 4) & 1) * 8 + (lane & 7);
                int cc = ks * 2 + ((lane >> 3) & 1);
                ldsm4(b[n2], SWA(bbase, rr, cc));
            }
            #pragma unroll
            for (int mf = 0; mf < 4; mf++)
                #pragma unroll
                for (int nf = 0; nf < 4; nf++)
                    mma16816(acc[mf][nf], a[mf],
                             b[nf >> 1][(nf & 1) * 2], b[nf >> 1][(nf & 1) * 2 + 1]);
        }
        __syncthreads();
    }
    #pragma unroll
    for (int mf = 0; mf < 4; mf++) {
        int grow = row0 + wm + mf * 16 + (lane >> 2);
        #pragma unroll
        for (int nf = 0; nf < 4; nf++) {
            int gcol = col0 + wn + nf * 8 + (lane & 3) * 2;
            float bx = 0.f, by = 0.f;
            if (has_bias) {
                float2 bb = *(const float2*)(bias + gcol);
                bx = bb.x; by = bb.y;
            }
            *(float2*)(C + (size_t)grow * N + gcol) =
                make_float2(acc[mf][nf][0] + bx, acc[mf][nf][1] + by);
            *(float2*)(C + (size_t)(grow + 8) * N + gcol) =
                make_float2(acc[mf][nf][2] + bx, acc[mf][nf][3] + by);
        }
    }
}

// ---------------------------------------------------------------------------
// RoPE tables + RoPE (no MUFU in hot pass)
// ---------------------------------------------------------------------------
__global__ __launch_bounds__(256) void rope_table_kernel(
    float* __restrict__ cosT, float* __restrict__ sinT)
{
    int idx = blockIdx.x * blockDim.x + threadIdx.x;  // NSEQ*DH
    int pos = idx >> 6, d = idx & 63;
    float fr = powf(10000.f, -(float)(d >> 1) * (1.f / 32.f));
    float a = (float)pos * fr;
    float s, c;
    sincosf(a, &s, &c);
    cosT[idx] = c;
    sinT[idx] = s;
}

__global__ __launch_bounds__(256) void rope_kernel(
    float* __restrict__ qkv,
    const float* __restrict__ cosT, const float* __restrict__ sinT)
{
    int idx = blockIdx.x * blockDim.x + threadIdx.x;
    int row = idx >> 10;
    int c2  = idx & 1023;
    int part = c2 >> 9;
    int wi = c2 & 511;
    int h = wi >> 5;
    int dlo = wi & 31;
    int pos = row & (NSEQ - 1);
    size_t base = (size_t)row * NQKV + part * INNER + h * DH;
    float v0 = qkv[base + dlo];
    float v1 = qkv[base + dlo + 32];
    float c0 = cosT[pos * DH + dlo],      s0 = sinT[pos * DH + dlo];
    float c1 = cosT[pos * DH + dlo + 32], s1 = sinT[pos * DH + dlo + 32];
    qkv[base + dlo]      = v0 * c0 - v1 * s0;
    qkv[base + dlo + 32] = v1 * c1 + v0 * s1;
}

// ---------------------------------------------------------------------------
// Tensor-core flash attention, fp16 hi/lo compensated (fp32-accurate).
// Block: 128 q-rows x head x batch, 8 warps (m16 each), 64-key tiles.
// ---------------------------------------------------------------------------
__global__ __launch_bounds__(256) void fa_kernel(
    const float* __restrict__ qkv, __half* __restrict__ o)
{
    __shared__ __align__(128) char sm[32768];
    uint32_t sb = smem_u32(sm);
    const uint32_t KHI = 0, KLO = 8192, VHI = 16384, VLO = 24576;
    const uint32_t QHI = 0, QLO = 16384;

    int tid = threadIdx.x, lane = tid & 31, wid = tid >> 5;
    int qt = blockIdx.x, h = blockIdx.y, b = blockIdx.z;
    const float QSC = 0.125f * 1.44269504089f;   // scale * log2(e) folded into Q

    // ---- stage Q (128x64), hi/lo, swizzled
    {
        const float* Qg = qkv + ((size_t)(b * NSEQ + qt * 128)) * NQKV + h * DH;
        #pragma unroll
        for (int t = 0; t < 4; t++) {
            int id = tid + t * 256;
            int r = id >> 3, g = id & 7;
            stage_hilo8(Qg + (size_t)r * NQKV + g * 8, QSC,
                        sm + QHI + SWZ(r, g), sm + QLO + SWZ(r, g));
        }
    }
    __syncthreads();
    uint32_t qhi[4][4], qlo[4][4];
    #pragma unroll
    for (int kt = 0; kt < 4; kt++) {
        int rr = wid * 16 + ((lane >> 3) & 1) * 8 + (lane & 7);
        int gg = 2 * kt + (lane >> 4);
        ldsm4(qhi[kt], sb + QHI + SWZ(rr, gg));
        ldsm4(qlo[kt], sb + QLO + SWZ(rr, gg));
    }
    __syncthreads();

    float accO[8][4];
    #pragma unroll
    for (int i = 0; i < 8; i++)
        #pragma unroll
        for (int j = 0; j < 4; j++) accO[i][j] = 0.f;
    float m0 = -1e30f, m1 = -1e30f, l0 = 0.f, l1 = 0.f;

    for (int s0 = 0; s0 < NSEQ; s0 += 64) {
        // ---- stage K,V (64x64 each), hi/lo
        #pragma unroll
        for (int t = 0; t < 4; t++) {
            int id = tid + t * 256;
            int tensor = id >> 9;          // 0=K, 1=V
            int r = (id >> 3) & 63, g = id & 7;
            const float* src = qkv + ((size_t)(b * NSEQ + s0 + r)) * NQKV
                             + INNER * (1 + tensor) + h * DH + g * 8;
            uint32_t dh = tensor ? VHI : KHI, dl = tensor ? VLO : KLO;
            stage_hilo8(src, 1.f, sm + dh + SWZ(r, g), sm + dl + SWZ(r, g));
        }
        __syncthreads();

        // ---- S = Q K^T (3-term compensated), S in log2 units
        float sAcc[8][4];
        #pragma unroll
        for (int i = 0; i < 8; i++)
            #pragma unroll
            for (int j = 0; j < 4; j++) sAcc[i][j] = 0.f;
        #pragma unroll
        for (int kt = 0; kt < 4; kt++) {
            #pragma unroll
            for (int g = 0; g < 4; g++) {
                uint32_t bh[4], bl[4];
                int rr = g * 16 + ((lane >> 4) & 1) * 8 + (lane & 7);
                int cc = kt * 2 + ((lane >> 3) & 1);
                ldsm4(bh, sb + KHI + SWZ(rr, cc));
                ldsm4(bl, sb + KLO + SWZ(rr, cc));
                mma16816(sAcc[2*g],   qhi[kt], bh[0], bh[1]);
                mma16816(sAcc[2*g+1], qhi[kt], bh[2], bh[3]);
                mma16816(sAcc[2*g],   qhi[kt], bl[0], bl[1]);
                mma16816(sAcc[2*g+1], qhi[kt], bl[2], bl[3]);
                mma16816(sAcc[2*g],   qlo[kt], bh[0], bh[1]);
                mma16816(sAcc[2*g+1], qlo[kt], bh[2], bh[3]);
            }
        }

        // ---- online softmax (FFMA exp2, no MUFU)
        float mx0 = -1e30f, mx1 = -1e30f;
        #pragma unroll
        for (int nt = 0; nt < 8; nt++) {
            mx0 = fmaxf(mx0, fmaxf(sAcc[nt][0], sAcc[nt][1]));
            mx1 = fmaxf(mx1, fmaxf(sAcc[nt][2], sAcc[nt][3]));
        }
        mx0 = fmaxf(mx0, __shfl_xor_sync(0xffffffffu, mx0, 1));
        mx0 = fmaxf(mx0, __shfl_xor_sync(0xffffffffu, mx0, 2));
        mx1 = fmaxf(mx1, __shfl_xor_sync(0xffffffffu, mx1, 1));
        mx1 = fmaxf(mx1, __shfl_xor_sync(0xffffffffu, mx1, 2));
        float mn0 = fmaxf(m0, mx0), mn1 = fmaxf(m1, mx1);
        float sc0 = exp2p(m0 - mn0), sc1 = exp2p(m1 - mn1);
        m0 = mn0; m1 = mn1;
        float rs0 = 0.f, rs1 = 0.f;
        #pragma unroll
        for (int nt = 0; nt < 8; nt++) {
            sAcc[nt][0] = exp2p(sAcc[nt][0] - m0); rs0 += sAcc[nt][0];
            sAcc[nt][1] = exp2p(sAcc[nt][1] - m0); rs0 += sAcc[nt][1];
            sAcc[nt][2] = exp2p(sAcc[nt][2] - m1); rs1 += sAcc[nt][2];
            sAcc[nt][3] = exp2p(sAcc[nt][3] - m1); rs1 += sAcc[nt][3];
        }
        rs0 += __shfl_xor_sync(0xffffffffu, rs0, 1);
        rs0 += __shfl_xor_sync(0xffffffffu, rs0, 2);
        rs1 += __shfl_xor_sync(0xffffffffu, rs1, 1);
        rs1 += __shfl_xor_sync(0xffffffffu, rs1, 2);
        l0 = l0 * sc0 + rs0;
        l1 = l1 * sc1 + rs1;
        #pragma unroll
        for (int dg = 0; dg < 8; dg++) {
            accO[dg][0] *= sc0; accO[dg][1] *= sc0;
            accO[dg][2] *= sc1; accO[dg][3] *= sc1;
        }

        // ---- P fragments (hi/lo) from S fragments (register recycle)
        uint32_t phi[4][4], plo[4][4];
        #pragma unroll
        for (int j = 0; j < 4; j++) {
            hilo2(sAcc[2*j][0],   sAcc[2*j][1],   phi[j][0], plo[j][0]);
            hilo2(sAcc[2*j][2],   sAcc[2*j][3],   phi[j][1], plo[j][1]);
            hilo2(sAcc[2*j+1][0], sAcc[2*j+1][1], phi[j][2], plo[j][2]);
            hilo2(sAcc[2*j+1][2], sAcc[2*j+1][3], phi[j][3], plo[j][3]);
        }

        // ---- O += P V (3-term compensated); V loaded via ldmatrix.trans
        #pragma unroll
        for (int j = 0; j < 4; j++) {
            #pragma unroll
            for (int dgp = 0; dgp < 4; dgp++) {
                uint32_t vh[4], vl[4];
                int rr = j * 16 + ((lane >> 3) & 1) * 8 + (lane & 7);
                int cc = dgp * 2 + (lane >> 4);
                ldsm4t(vh, sb + VHI + SWZ(rr, cc));
                ldsm4t(vl, sb + VLO + SWZ(rr, cc));
                mma16816(accO[2*dgp],   phi[j], vh[0], vh[1]);
                mma16816(accO[2*dgp+1], phi[j], vh[2], vh[3]);
                mma16816(accO[2*dgp],   phi[j], vl[0], vl[1]);
                mma16816(accO[2*dgp+1], phi[j], vl[2], vl[3]);
                mma16816(accO[2*dgp],   plo[j], vh[0], vh[1]);
                mma16816(accO[2*dgp+1], plo[j], vh[2], vh[3]);
            }
        }
        __syncthreads();
    }

    // ---- epilogue
    float inv0 = 1.f / l0, inv1 = 1.f / l1;
    int row = b * NSEQ + qt * 128 + wid * 16 + (lane >> 2);
    __half* op0 = o + (size_t)row * INNER + h * DH + 2 * (lane & 3);
    __half* op1 = op0 + (size_t)8 * INNER;
    #pragma unroll
    for (int dg = 0; dg < 8; dg++) {
        *(__half2*)(op0 + dg * 8) = __floats2half2_rn(accO[dg][0] * inv0, accO[dg][1] * inv0);
        *(__half2*)(op1 + dg * 8) = __floats2half2_rn(accO[dg][2] * inv1, accO[dg][3] * inv1);
    }
}

// ---------------------------------------------------------------------------
extern "C" void kernel_launch(void* const* d_in, const int* in_sizes, int n_in,
                              void* d_out, int out_size)
{
    const float* x     = (const float*)d_in[0];
    const float* ln_g  = (const float*)d_in[1];
    const float* ln_b  = (const float*)d_in[2];
    const float* w_qkv = (const float*)d_in[3];
    const float* w_out = (const float*)d_in[4];
    const float* b_out = (const float*)d_in[5];
    float* out = (float*)d_out;

    __half *xn_h, *o_h, *wqkvT_h, *woutT_h;
    float *qkv, *cosT, *sinT;
    cudaGetSymbolAddress((void**)&xn_h,    g_xn_h);
    cudaGetSymbolAddress((void**)&qkv,     g_qkv);
    cudaGetSymbolAddress((void**)&o_h,     g_o_h);
    cudaGetSymbolAddress((void**)&wqkvT_h, g_wqkvT_h);
    cudaGetSymbolAddress((void**)&woutT_h, g_woutT_h);
    cudaGetSymbolAddress((void**)&cosT,    g_cosT);
    cudaGetSymbolAddress((void**)&sinT,    g_sinT);

    ln_kernel<<<ROWS, 256>>>(x, ln_g, ln_b, xn_h);
    transpose_cvt_kernel<<<dim3(NQKV / 32, DIM / 32), 256>>>(w_qkv, wqkvT_h, DIM, NQKV);
    transpose_cvt_kernel<<<dim3(DIM / 32, INNER / 32), 256>>>(w_out, woutT_h, INNER, DIM);
    rope_table_kernel<<<(NSEQ * DH) / 256, 256>>>(cosT, sinT);

    hgemm<<<dim3(NQKV / 128, ROWS / 128), 256>>>(
        xn_h, wqkvT_h, nullptr, qkv, ROWS, NQKV, DIM, 0);

    rope_kernel<<<(ROWS * 1024) / 256, 256>>>(qkv, cosT, sinT);

    fa_kernel<<<dim3(NSEQ / 128, HEADS, BATCH), 256>>>(qkv, o_h);

    hgemm<<<dim3(DIM / 128, ROWS / 128), 256>>>(
        o_h, woutT_h, b_out, out, ROWS, DIM, INNER, 1);
}